// round 1
// baseline (speedup 1.0000x reference)
#include <cuda_runtime.h>
#include <stdint.h>
#include <math.h>

#define BATCH 32
#define SEQ   8400
#define NLAB  80
#define DIM   256
#define NQ    300

// Scratch (allocation-free per harness rules)
__device__ float g_scores[BATCH * SEQ];
__device__ int   g_topk[BATCH * NQ];

// ---------------------------------------------------------------------------
// Kernel 1: scores[b][s] = max over 80 labels. One warp per row, coalesced.
// ---------------------------------------------------------------------------
__global__ void scores_kernel(const float* __restrict__ cls) {
    int gwarp = (blockIdx.x * blockDim.x + threadIdx.x) >> 5;
    int lane  = threadIdx.x & 31;
    if (gwarp >= BATCH * SEQ) return;
    const float* row = cls + (size_t)gwarp * NLAB;
    float m = -INFINITY;
    #pragma unroll
    for (int e = lane; e < NLAB; e += 32) m = fmaxf(m, row[e]);
    #pragma unroll
    for (int o = 16; o > 0; o >>= 1) m = fmaxf(m, __shfl_xor_sync(0xFFFFFFFFu, m, o));
    if (lane == 0) g_scores[gwarp] = m;
}

// ---------------------------------------------------------------------------
// Kernel 2: per-batch exact top-300 in sorted (descending, lower-index-first)
// order via 64-bit radix select + bitonic sort of the 300 survivors.
// Key = (sortable(score) << 32) | (SEQ-1-s)  -> all keys unique, order matches
// jax.lax.top_k exactly.
// ---------------------------------------------------------------------------
__device__ __forceinline__ unsigned int f32_sortable(float v) {
    unsigned int u = __float_as_uint(v);
    return (u & 0x80000000u) ? ~u : (u | 0x80000000u);  // ascending-order uint
}

__global__ void __launch_bounds__(1024) topk_kernel() {
    __shared__ unsigned int       s_vals[SEQ];   // 33.6 KB: sortable score bits
    __shared__ unsigned long long s_cand[512];   // 4 KB
    __shared__ unsigned int       s_hist[256];   // 1 KB
    __shared__ unsigned long long s_prefix;
    __shared__ unsigned int       s_remaining;
    __shared__ unsigned int       s_cnt;

    const int b   = blockIdx.x;
    const int tid = threadIdx.x;

    for (int s = tid; s < SEQ; s += 1024)
        s_vals[s] = f32_sortable(g_scores[b * SEQ + s]);
    if (tid == 0) { s_prefix = 0ull; s_remaining = NQ; s_cnt = 0; }
    __syncthreads();

    // 8 passes of 8-bit MSD radix select for the key of rank NQ (descending).
    for (int pass = 0; pass < 8; ++pass) {
        const int shift = 56 - 8 * pass;
        if (tid < 256) s_hist[tid] = 0;
        __syncthreads();
        const unsigned long long pref = s_prefix;

        for (int s0 = 0; s0 < SEQ; s0 += 1024) {
            int s = s0 + tid;
            bool valid = false;
            unsigned int digit = 0x1FFu;  // sentinel for inactive lanes
            if (s < SEQ) {
                unsigned long long k =
                    ((unsigned long long)s_vals[s] << 32) | (unsigned int)(SEQ - 1 - s);
                bool match = (pass == 0) || ((k >> (shift + 8)) == pref);
                if (match) { valid = true; digit = (unsigned int)(k >> shift) & 0xFFu; }
            }
            // warp-aggregated histogram update (early passes are heavily skewed)
            unsigned mask = __match_any_sync(0xFFFFFFFFu, digit);
            if (valid && ((unsigned)(__ffs(mask) - 1) == (threadIdx.x & 31u)))
                atomicAdd(&s_hist[digit], (unsigned)__popc(mask));
        }
        __syncthreads();

        if (tid == 0) {
            unsigned int cum = 0, rem = s_remaining;
            for (int d = 255; d >= 0; --d) {
                unsigned int c = s_hist[d];
                if (cum + c >= rem) {
                    s_prefix = (s_prefix << 8) | (unsigned long long)d;
                    s_remaining = rem - cum;
                    break;
                }
                cum += c;
            }
        }
        __syncthreads();
    }

    // Collect the exactly-NQ keys >= threshold (keys are unique).
    const unsigned long long thr = s_prefix;
    if (tid >= NQ && tid < 512) s_cand[tid] = 0ull;  // pad for bitonic
    for (int s = tid; s < SEQ; s += 1024) {
        unsigned long long k =
            ((unsigned long long)s_vals[s] << 32) | (unsigned int)(SEQ - 1 - s);
        if (k >= thr) {
            unsigned int p = atomicAdd(&s_cnt, 1u);
            if (p < 512) s_cand[p] = k;
        }
    }
    __syncthreads();

    // Bitonic sort 512 keys descending. Threads 0..511 each own one slot.
    for (int k = 2; k <= 512; k <<= 1) {
        for (int j = k >> 1; j > 0; j >>= 1) {
            if (tid < 512) {
                int ixj = tid ^ j;
                if (ixj > tid) {
                    unsigned long long a = s_cand[tid], c = s_cand[ixj];
                    bool desc = ((tid & k) == 0);
                    bool sw = desc ? (a < c) : (a > c);
                    if (sw) { s_cand[tid] = c; s_cand[ixj] = a; }
                }
            }
            __syncthreads();
        }
    }

    if (tid < NQ) {
        unsigned long long k = s_cand[tid];
        int s = SEQ - 1 - (int)(unsigned int)(k & 0xFFFFFFFFull);
        g_topk[b * NQ + tid] = s;
    }
}

// ---------------------------------------------------------------------------
// Kernel 3: gather all four outputs. One block per (b, q).
// Output layout (flattened tuple, return order):
//   [0]                      init_reference_points  (B,NQ,4)
//   [B*NQ*4]                 target                 (B,NQ,256)
//   [B*NQ*4 + B*NQ*256]      enc_topk_logits        (B,NQ,80)
//   [.. + B*NQ*80]           enc_topk_bboxes        (B,NQ,4)
// ---------------------------------------------------------------------------
__global__ void gather_kernel(const float* __restrict__ cls,
                              const float* __restrict__ coord,
                              const float* __restrict__ mem,
                              float* __restrict__ out) {
    const int bq = blockIdx.x;
    const int b  = bq / NQ;
    const int t  = threadIdx.x;
    const int s  = g_topk[bq];
    const size_t src = (size_t)b * SEQ + (size_t)s;

    float* out_ref  = out;
    float* out_tgt  = out + (size_t)BATCH * NQ * 4;
    float* out_log  = out_tgt + (size_t)BATCH * NQ * DIM;
    float* out_bbox = out_log + (size_t)BATCH * NQ * NLAB;

    if (t < 4) {
        float v = coord[src * 4 + t];
        out_ref [(size_t)bq * 4 + t] = v;
        out_bbox[(size_t)bq * 4 + t] = 1.0f / (1.0f + __expf(-v));
    }
    if (t < NLAB)
        out_log[(size_t)bq * NLAB + t] = cls[src * NLAB + t];
    if (t < DIM / 4) {
        const float4* m4 = (const float4*)(mem + src * DIM);
        float4*       o4 = (float4*)(out_tgt + (size_t)bq * DIM);
        o4[t] = m4[t];
    }
}

// ---------------------------------------------------------------------------
extern "C" void kernel_launch(void* const* d_in, const int* in_sizes, int n_in,
                              void* d_out, int out_size) {
    const float* cls   = (const float*)d_in[0];  // (32, 8400, 80)
    const float* coord = (const float*)d_in[1];  // (32, 8400, 4)
    const float* mem   = (const float*)d_in[2];  // (32, 8400, 256)
    // d_in[3] (sources_last_element) is unused by the reference outputs.
    float* out = (float*)d_out;

    const int rows = BATCH * SEQ;                 // 268800 warps, 8 warps/block
    scores_kernel<<<(rows * 32 + 255) / 256, 256>>>(cls);
    topk_kernel<<<BATCH, 1024>>>();
    gather_kernel<<<BATCH * NQ, 128>>>(cls, coord, mem, out);
}

// round 2
// speedup vs baseline: 2.3881x; 2.3881x over previous
#include <cuda_runtime.h>
#include <stdint.h>
#include <math.h>

#define BATCH 32
#define SEQ   8400
#define NLAB  80
#define DIM   256
#define NQ    300
#define CAND  512

// Scratch (allocation-free per harness rules)
__device__ unsigned int g_scores_u[BATCH * SEQ];  // sortable-uint scores
__device__ int          g_topk[BATCH * NQ];

__device__ __forceinline__ unsigned int f32_sortable(float v) {
    unsigned int u = __float_as_uint(v);
    return (u & 0x80000000u) ? ~u : (u | 0x80000000u);  // ascending-order uint
}

// ---------------------------------------------------------------------------
// Kernel 1: scores[b][s] = max over 80 labels, stored as sortable uint.
// One warp handles 4 rows; each active lane (0..19) does one float4 load per
// row -> 4 independent LDG.128 in flight before the shfl reductions.
// ---------------------------------------------------------------------------
__global__ void scores_kernel(const float* __restrict__ cls) {
    const int warp = blockIdx.x * 8 + (threadIdx.x >> 5);
    const int lane = threadIdx.x & 31;
    const int r0   = warp * 4;
    if (r0 >= BATCH * SEQ) return;

    const float4* base = (const float4*)cls;  // 20 float4 per row
    float m[4];
    #pragma unroll
    for (int i = 0; i < 4; ++i) {
        float4 v;
        if (lane < 20) v = __ldg(&base[(size_t)(r0 + i) * 20 + lane]);
        else           v = make_float4(-INFINITY, -INFINITY, -INFINITY, -INFINITY);
        m[i] = fmaxf(fmaxf(v.x, v.y), fmaxf(v.z, v.w));
    }
    #pragma unroll
    for (int i = 0; i < 4; ++i) {
        #pragma unroll
        for (int o = 16; o > 0; o >>= 1)
            m[i] = fmaxf(m[i], __shfl_xor_sync(0xFFFFFFFFu, m[i], o));
    }
    if (lane == 0) {
        uint4 w;
        w.x = f32_sortable(m[0]); w.y = f32_sortable(m[1]);
        w.z = f32_sortable(m[2]); w.w = f32_sortable(m[3]);
        *(uint4*)&g_scores_u[r0] = w;  // r0 multiple of 4 -> 16B aligned
    }
}

// ---------------------------------------------------------------------------
// Kernel 2: per-batch exact top-300, sorted desc, jax tie-break.
// Two 11-bit radix passes (2048-bin smem histogram) find the top-22-bit
// threshold; threshold-bin selection is a fully parallel block suffix scan.
// Candidates (>= threshold, ~302 of them) are bitonic-sorted as 64-bit keys
// (sortable_score << 32) | (SEQ-1-s)  -> unique keys, lower index wins ties.
// ---------------------------------------------------------------------------
__global__ void __launch_bounds__(1024) topk_kernel() {
    __shared__ unsigned int       s_vals[SEQ];     // 33600 B
    __shared__ unsigned int       s_hist[2048];    //  8192 B
    __shared__ unsigned long long s_cand[CAND];    //  4096 B
    __shared__ unsigned int       s_warp[32];
    __shared__ unsigned int       s_above[32];
    __shared__ unsigned int       s_bin, s_cntGT, s_need, s_cnt;

    const int b    = blockIdx.x;
    const int tid  = threadIdx.x;
    const int lane = tid & 31;
    const int wid  = tid >> 5;

    for (int s = tid; s < SEQ; s += 1024)
        s_vals[s] = g_scores_u[b * SEQ + s];
    if (tid == 0) { s_need = NQ; s_cnt = 0; }

    unsigned int prefix = 0;  // pass-0 winning bin (top 11 bits)
    for (int pass = 0; pass < 2; ++pass) {
        const int shift = (pass == 0) ? 21 : 10;
        for (int i = tid; i < 2048; i += 1024) s_hist[i] = 0;
        __syncthreads();

        // histogram build (warp-aggregated: bins are heavily clustered)
        for (int s0 = 0; s0 < SEQ; s0 += 1024) {
            int s = s0 + tid;
            unsigned int digit = 0xFFFFu;  // sentinel
            bool valid = false;
            if (s < SEQ) {
                unsigned int v = s_vals[s];
                if (pass == 0 || (v >> 21) == prefix) {
                    valid = true;
                    digit = (v >> shift) & 0x7FFu;
                }
            }
            unsigned mask = __match_any_sync(0xFFFFFFFFu, digit);
            if (valid && (unsigned)(__ffs(mask) - 1) == (unsigned)lane)
                atomicAdd(&s_hist[digit], (unsigned)__popc(mask));
        }
        __syncthreads();

        // parallel suffix selection: thread t owns bins {2t, 2t+1}
        unsigned int c0 = s_hist[2 * tid];
        unsigned int c1 = s_hist[2 * tid + 1];
        unsigned int L  = c0 + c1;
        unsigned int inc = L;  // inclusive suffix sum within warp
        #pragma unroll
        for (int o = 1; o < 32; o <<= 1) {
            unsigned int t = __shfl_down_sync(0xFFFFFFFFu, inc, o);
            if (lane + o < 32) inc += t;
        }
        if (lane == 0) s_warp[wid] = inc;  // warp total
        __syncthreads();
        if (tid < 32) {
            unsigned int v  = s_warp[tid];
            unsigned int i2 = v;
            #pragma unroll
            for (int o = 1; o < 32; o <<= 1) {
                unsigned int t = __shfl_down_sync(0xFFFFFFFFu, i2, o);
                if (tid + o < 32) i2 += t;
            }
            s_above[tid] = i2 - v;  // sum of higher warps
        }
        __syncthreads();

        const unsigned int need = s_need;
        unsigned int G = s_above[wid] + (inc - L);  // count strictly above my bins
        if (G < need && need <= G + c1) { s_bin = 2 * tid + 1; s_cntGT = G; }
        unsigned int G2 = G + c1;
        if (G2 < need && need <= G2 + c0) { s_bin = 2 * tid; s_cntGT = G2; }
        __syncthreads();

        if (pass == 0) {
            prefix = s_bin;
            if (tid == 0) s_need = need - s_cntGT;
            __syncthreads();
        }
    }

    const unsigned int T22 = (prefix << 11) | s_bin;  // top-22-bit threshold

    if (tid < CAND) s_cand[tid] = 0ull;  // padding sinks in descending sort
    __syncthreads();

    for (int s = tid; s < SEQ; s += 1024) {
        unsigned int v = s_vals[s];
        if ((v >> 10) >= T22) {
            unsigned int p = atomicAdd(&s_cnt, 1u);
            if (p < CAND)
                s_cand[p] = ((unsigned long long)v << 32) |
                            (unsigned int)(SEQ - 1 - s);
        }
    }
    __syncthreads();

    // bitonic sort 512 keys, descending
    for (int k = 2; k <= CAND; k <<= 1) {
        for (int j = k >> 1; j > 0; j >>= 1) {
            if (tid < CAND) {
                int ixj = tid ^ j;
                if (ixj > tid) {
                    unsigned long long a = s_cand[tid], c = s_cand[ixj];
                    bool desc = ((tid & k) == 0);
                    if (desc ? (a < c) : (a > c)) {
                        s_cand[tid] = c; s_cand[ixj] = a;
                    }
                }
            }
            __syncthreads();
        }
    }

    if (tid < NQ) {
        int s = SEQ - 1 - (int)(unsigned int)(s_cand[tid] & 0xFFFFFFFFull);
        g_topk[b * NQ + tid] = s;
    }
}

// ---------------------------------------------------------------------------
// Kernel 3: gather the four outputs. One block per (b, q).
// Output layout (flattened tuple, return order):
//   [0]                  init_reference_points (B,NQ,4)
//   [+B*NQ*4]            target                (B,NQ,256)
//   [+B*NQ*256]          enc_topk_logits       (B,NQ,80)
//   [+B*NQ*80]           enc_topk_bboxes       (B,NQ,4)
// ---------------------------------------------------------------------------
__global__ void gather_kernel(const float* __restrict__ cls,
                              const float* __restrict__ coord,
                              const float* __restrict__ mem,
                              float* __restrict__ out) {
    const int bq = blockIdx.x;
    const int b  = bq / NQ;
    const int t  = threadIdx.x;
    const int s  = g_topk[bq];
    const size_t src = (size_t)b * SEQ + (size_t)s;

    float* out_ref  = out;
    float* out_tgt  = out + (size_t)BATCH * NQ * 4;
    float* out_log  = out_tgt + (size_t)BATCH * NQ * DIM;
    float* out_bbox = out_log + (size_t)BATCH * NQ * NLAB;

    if (t < 4) {
        float v = coord[src * 4 + t];
        out_ref [(size_t)bq * 4 + t] = v;
        out_bbox[(size_t)bq * 4 + t] = 1.0f / (1.0f + __expf(-v));
    }
    if (t < NLAB)
        out_log[(size_t)bq * NLAB + t] = cls[src * NLAB + t];
    if (t < DIM / 4) {
        const float4* m4 = (const float4*)(mem + src * DIM);
        float4*       o4 = (float4*)(out_tgt + (size_t)bq * DIM);
        o4[t] = m4[t];
    }
}

// ---------------------------------------------------------------------------
extern "C" void kernel_launch(void* const* d_in, const int* in_sizes, int n_in,
                              void* d_out, int out_size) {
    const float* cls   = (const float*)d_in[0];  // (32, 8400, 80)
    const float* coord = (const float*)d_in[1];  // (32, 8400, 4)
    const float* mem   = (const float*)d_in[2];  // (32, 8400, 256)
    float* out = (float*)d_out;

    // 268800 rows, 4 rows/warp, 8 warps/block -> 8400 blocks
    scores_kernel<<<8400, 256>>>(cls);
    topk_kernel<<<BATCH, 1024>>>();
    gather_kernel<<<BATCH * NQ, 128>>>(cls, coord, mem, out);
}

// round 3
// speedup vs baseline: 2.4980x; 1.0460x over previous
#include <cuda_runtime.h>
#include <stdint.h>
#include <math.h>

#define BATCH 32
#define SEQ   8400
#define NLAB  80
#define DIM   256
#define NQ    300
#define CAND  512
#define RPB   48      // rows per block in scores kernel

// Scratch (allocation-free per harness rules)
__device__ unsigned int g_scores_u[BATCH * SEQ];  // sortable-uint scores
__device__ int          g_topk[BATCH * NQ];

__device__ __forceinline__ unsigned int f32_sortable(float v) {
    unsigned int u = __float_as_uint(v);
    return (u & 0x80000000u) ? ~u : (u | 0x80000000u);  // ascending-order uint
}

// ---------------------------------------------------------------------------
// Kernel 1: scores[b][s] = max over 80 labels, stored as sortable uint.
// Phase 1: 256 threads load 960 contiguous float4 (48 rows) fully coalesced,
//          write per-float4 maxes to smem. Phase 2: 4 lanes/row reduce 20
//          partials (stride-5 smem -> conflict-free) + 2 shfls.
// ---------------------------------------------------------------------------
__global__ void __launch_bounds__(256) scores_kernel(const float* __restrict__ cls) {
    __shared__ float part[RPB * 20];  // 960 floats

    const int t = threadIdx.x;
    const float4* base = (const float4*)cls + (size_t)blockIdx.x * (RPB * 20);

    #pragma unroll
    for (int i = 0; i < 4; ++i) {
        int idx = t + 256 * i;
        if (idx < RPB * 20) {
            float4 v = __ldg(&base[idx]);
            part[idx] = fmaxf(fmaxf(v.x, v.y), fmaxf(v.z, v.w));
        }
    }
    __syncthreads();

    if (t < RPB * 4) {                 // 192 threads: 4 per row
        int row = t >> 2;
        int p   = t & 3;
        const float* q = &part[row * 20 + p * 5];
        float m = q[0];
        #pragma unroll
        for (int j = 1; j < 5; ++j) m = fmaxf(m, q[j]);
        m = fmaxf(m, __shfl_xor_sync(0xFFFFFFFFu, m, 1));
        m = fmaxf(m, __shfl_xor_sync(0xFFFFFFFFu, m, 2));
        if (p == 0)
            g_scores_u[blockIdx.x * RPB + row] = f32_sortable(m);
    }
}

// ---------------------------------------------------------------------------
// Kernel 2: per-batch exact top-300, sorted desc, jax tie-break.
// Values live in registers (8 vectorized + 1 tail per thread). The 22-bit
// threshold is found by binary search with atomic-free block count-reductions
// (robust to the heavy value clustering that killed the histogram approach).
// Candidates (>= threshold) are compacted by a block prefix scan, then
// bitonic-sorted as (score<<32 | SEQ-1-s) keys.
// ---------------------------------------------------------------------------
__global__ void __launch_bounds__(1024) topk_kernel() {
    __shared__ unsigned int       s_warp[32];
    __shared__ unsigned int       s_woff[32];
    __shared__ unsigned int       s_total;
    __shared__ unsigned long long s_cand[CAND];

    const int b    = blockIdx.x;
    const int tid  = threadIdx.x;
    const int lane = tid & 31;
    const int wid  = tid >> 5;
    const unsigned FULL = 0xFFFFFFFFu;

    const unsigned int* sc = g_scores_u + b * SEQ;

    // ---- load 9 values into registers (8192 via uint4 + 208 tail) ----
    uint4 va = ((const uint4*)sc)[tid];
    uint4 vb = ((const uint4*)sc)[tid + 1024];
    const bool hasTail = (tid < SEQ - 8192);           // 208
    unsigned int vt = hasTail ? sc[8192 + tid] : 0u;

    unsigned int vv[9];
    int si[9];
    vv[0]=va.x; vv[1]=va.y; vv[2]=va.z; vv[3]=va.w;
    vv[4]=vb.x; vv[5]=vb.y; vv[6]=vb.z; vv[7]=vb.w;
    vv[8]=vt;
    #pragma unroll
    for (int k = 0; k < 4; ++k) { si[k] = 4*tid + k; si[4+k] = 4096 + 4*tid + k; }
    si[8] = 8192 + tid;

    // ---- block max (sets search upper bound) ----
    unsigned int mx = 0;
    #pragma unroll
    for (int k = 0; k < 8; ++k) mx = max(mx, vv[k]);
    if (hasTail) mx = max(mx, vv[8]);
    #pragma unroll
    for (int o = 16; o > 0; o >>= 1) mx = max(mx, __shfl_xor_sync(FULL, mx, o));
    if (lane == 0) s_warp[wid] = mx;
    __syncthreads();
    if (tid < 32) {
        unsigned int m2 = s_warp[tid];
        #pragma unroll
        for (int o = 16; o > 0; o >>= 1) m2 = max(m2, __shfl_xor_sync(FULL, m2, o));
        if (tid == 0) s_total = m2;
    }
    __syncthreads();
    const unsigned int M = s_total;

    // ---- binary search for largest 22-bit T with count(v>>10 >= T) >= NQ ----
    unsigned int lo = 0, hi = (M >> 10) + 1;
    // first probe close below hi (values cluster near the max)
    unsigned int mid = (hi > 16384u) ? hi - 16384u : ((lo + hi) >> 1);

    while (true) {
        const unsigned int thr = mid << 10;
        int c = 0;
        #pragma unroll
        for (int k = 0; k < 8; ++k) c += (vv[k] >= thr);
        c += (hasTail && vv[8] >= thr);
        #pragma unroll
        for (int o = 16; o > 0; o >>= 1) c += __shfl_xor_sync(FULL, c, o);
        if (lane == 0) s_warp[wid] = (unsigned)c;
        __syncthreads();
        if (tid < 32) {
            unsigned int t2 = s_warp[tid];
            #pragma unroll
            for (int o = 16; o > 0; o >>= 1) t2 += __shfl_xor_sync(FULL, t2, o);
            if (tid == 0) s_total = t2;
        }
        __syncthreads();
        if (s_total >= NQ) lo = mid; else hi = mid;
        if (hi - lo <= 1) break;
        mid = (lo + hi) >> 1;
    }
    const unsigned int T = lo << 10;   // v >= T  <=>  (v>>10) >= lo

    // ---- compact candidates via block prefix scan (no atomics) ----
    if (tid < CAND) s_cand[tid] = 0ull;   // padding sinks in descending sort

    bool hit[9];
    int myc = 0;
    #pragma unroll
    for (int k = 0; k < 8; ++k) { hit[k] = (vv[k] >= T); myc += hit[k]; }
    hit[8] = hasTail && (vv[8] >= T); myc += hit[8];

    int inc = myc;
    #pragma unroll
    for (int o = 1; o < 32; o <<= 1) {
        int t2 = __shfl_up_sync(FULL, inc, o);
        if (lane >= o) inc += t2;
    }
    if (lane == 31) s_warp[wid] = (unsigned)inc;
    __syncthreads();
    if (tid < 32) {
        unsigned int v = s_warp[tid];
        unsigned int i2 = v;
        #pragma unroll
        for (int o = 1; o < 32; o <<= 1) {
            unsigned int t2 = __shfl_up_sync(FULL, i2, o);
            if (tid >= o) i2 += t2;
        }
        s_woff[tid] = i2 - v;   // exclusive warp offsets
    }
    __syncthreads();

    int pos = (int)s_woff[wid] + (inc - myc);
    #pragma unroll
    for (int k = 0; k < 9; ++k) {
        if (hit[k]) {
            if (pos < CAND)
                s_cand[pos] = ((unsigned long long)vv[k] << 32) |
                              (unsigned int)(SEQ - 1 - si[k]);
            ++pos;
        }
    }
    __syncthreads();

    // ---- bitonic sort 512 keys, descending ----
    for (int k = 2; k <= CAND; k <<= 1) {
        for (int j = k >> 1; j > 0; j >>= 1) {
            if (tid < CAND) {
                int ixj = tid ^ j;
                if (ixj > tid) {
                    unsigned long long a = s_cand[tid], c = s_cand[ixj];
                    bool desc = ((tid & k) == 0);
                    if (desc ? (a < c) : (a > c)) {
                        s_cand[tid] = c; s_cand[ixj] = a;
                    }
                }
            }
            __syncthreads();
        }
    }

    if (tid < NQ) {
        int s = SEQ - 1 - (int)(unsigned int)(s_cand[tid] & 0xFFFFFFFFull);
        g_topk[b * NQ + tid] = s;
    }
}

// ---------------------------------------------------------------------------
// Kernel 3: gather the four outputs. One block per (b, q).
// Output layout (flattened tuple, return order):
//   [0]            init_reference_points (B,NQ,4)
//   [+B*NQ*4]      target                (B,NQ,256)
//   [+B*NQ*256]    enc_topk_logits       (B,NQ,80)
//   [+B*NQ*80]     enc_topk_bboxes       (B,NQ,4)
// ---------------------------------------------------------------------------
__global__ void gather_kernel(const float* __restrict__ cls,
                              const float* __restrict__ coord,
                              const float* __restrict__ mem,
                              float* __restrict__ out) {
    const int bq = blockIdx.x;
    const int b  = bq / NQ;
    const int t  = threadIdx.x;
    const int s  = g_topk[bq];
    const size_t src = (size_t)b * SEQ + (size_t)s;

    float* out_ref  = out;
    float* out_tgt  = out + (size_t)BATCH * NQ * 4;
    float* out_log  = out_tgt + (size_t)BATCH * NQ * DIM;
    float* out_bbox = out_log + (size_t)BATCH * NQ * NLAB;

    if (t < 4) {
        float v = coord[src * 4 + t];
        out_ref [(size_t)bq * 4 + t] = v;
        out_bbox[(size_t)bq * 4 + t] = 1.0f / (1.0f + __expf(-v));
    }
    if (t < NLAB)
        out_log[(size_t)bq * NLAB + t] = cls[src * NLAB + t];
    if (t < DIM / 4) {
        const float4* m4 = (const float4*)(mem + src * DIM);
        float4*       o4 = (float4*)(out_tgt + (size_t)bq * DIM);
        o4[t] = m4[t];
    }
}

// ---------------------------------------------------------------------------
extern "C" void kernel_launch(void* const* d_in, const int* in_sizes, int n_in,
                              void* d_out, int out_size) {
    const float* cls   = (const float*)d_in[0];  // (32, 8400, 80)
    const float* coord = (const float*)d_in[1];  // (32, 8400, 4)
    const float* mem   = (const float*)d_in[2];  // (32, 8400, 256)
    float* out = (float*)d_out;

    scores_kernel<<<(BATCH * SEQ) / RPB, 256>>>(cls);   // 5600 blocks
    topk_kernel<<<BATCH, 1024>>>();
    gather_kernel<<<BATCH * NQ, 128>>>(cls, coord, mem, out);
}